// round 14
// baseline (speedup 1.0000x reference)
#include <cuda_runtime.h>
#include <cuda_bf16.h>

// CoPEModel GCN on GB300.
// CSR-build (rank-recorded histogram -> lookback scan -> atomic-free scatter
// fused with x->bf16 conversion) + bf16-gather pull-mode SpMM with rs_out
// pre-scaled into features + f32x2 GEMM with fused BN stats + fused readout.
// Inputs (metadata order): x, src, dst, W1, b1, g1, be1, W2, b2, g2, be2, Wc, bc
// Output: [1,2] float32.

#define NMAX 100000
#define EMAX 1600000

#define SCAN_BLOCKS 128
#define SCAN_TPB    256
#define SCAN_T      (SCAN_BLOCKS * SCAN_TPB)   // 32768 scan threads
#define SCAN_CHUNK  4                          // ceil(100000/32768)

#define EPSV 1e-5f

typedef unsigned long long ull;

// ---- zero-initialized-per-launch blob (single memset node) ----
// [0,N): deg_out  [N,2N): deg_in
// [2N..): s1(64) q1(64) s2(64) q2(64) colsum(64) done(1) pad.. flags(128)
#define OFF_DEG_OUT 0
#define OFF_DEG_IN  NMAX
#define OFF_STATS   (2 * NMAX)
#define OFF_FLAGS   (OFF_STATS + 384)
#define BLOB_INTS   (OFF_FLAGS + SCAN_BLOCKS)
__device__ __align__(16) int g_blob[BLOB_INTS];

__device__ __align__(16) float g_rs_out[NMAX];
__device__ __align__(16) float g_rs_in[NMAX];
__device__ __align__(16) int   g_row_ptr[NMAX + 1];
__device__ __align__(16) int   g_rank[EMAX];            // intra-dst rank of each edge
__device__ __align__(16) int   g_col[EMAX];             // CSR column (src) indices
__device__ __align__(16) __nv_bfloat162 g_xb[(size_t)NMAX * 32];  // bf16 rs_out*x
__device__ __align__(16) __nv_bfloat162 g_ab[(size_t)NMAX * 32];  // bf16 rs_out*relu(bn(h1))
__device__ __align__(16) float g_m[(size_t)NMAX * 64];  // aggregated messages
__device__ __align__(16) float g_h[(size_t)NMAX * 64];  // post-GEMM

// ---------------- f32x2 helpers ----------------
__device__ __forceinline__ void f2unpack(ull v, float& a, float& b) {
    asm("mov.b64 {%0, %1}, %2;" : "=f"(a), "=f"(b) : "l"(v));
}
__device__ __forceinline__ ull f2fma(ull a, ull b, ull c) {
    ull d; asm("fma.rn.f32x2 %0, %1, %2, %3;" : "=l"(d) : "l"(a), "l"(b), "l"(c)); return d;
}

// ---------------- graph preprocessing ----------------

// Degree histogram; the deg_in atomic RETURNS this edge's rank within its dst
// bucket, recorded coalesced — the scatter then needs no atomic at all.
__global__ void k_deg(const int* __restrict__ src, const int* __restrict__ dst, int e) {
    int i = blockIdx.x * blockDim.x + threadIdx.x;
    if (i < e) {
        g_rank[i] = atomicAdd(&g_blob[OFF_DEG_IN + dst[i]], 1);
        atomicAdd(&g_blob[OFF_DEG_OUT + src[i]], 1);
    }
}

// Single-kernel exclusive scan of deg_in -> row_ptr via decoupled lookback.
// All SCAN_BLOCKS=128 blocks are co-resident (<=148 SMs), so spinning on
// predecessor flags cannot deadlock. Also computes rsqrt of both degrees.
__global__ void k_scan(int n) {
    __shared__ int sh[SCAN_TPB];
    int t = threadIdx.x;
    int bid = blockIdx.x;
    int g = bid * SCAN_TPB + t;
    int beg = g * SCAN_CHUNK;
    int end = min(beg + SCAN_CHUNK, n);
    int cnt = max(end - beg, 0);

    int d[SCAN_CHUNK];
    int s = 0;
    #pragma unroll
    for (int i = 0; i < SCAN_CHUNK; i++) {
        d[i] = 0;
        if (i < cnt) {
            int di = g_blob[OFF_DEG_IN + beg + i];
            d[i] = di;
            s += di;
            g_rs_in[beg + i]  = rsqrtf((float)max(di, 1));
            g_rs_out[beg + i] = rsqrtf((float)max(g_blob[OFF_DEG_OUT + beg + i], 1));
        }
    }

    // block-level inclusive scan -> exclusive per-thread prefix + block total
    sh[t] = s;
    __syncthreads();
    for (int off = 1; off < SCAN_TPB; off <<= 1) {
        int v = (t >= off) ? sh[t - off] : 0;
        __syncthreads();
        sh[t] += v;
        __syncthreads();
    }
    int tpre = sh[t] - s;
    if (t == SCAN_TPB - 1) atomicExch(&g_blob[OFF_FLAGS + bid], sh[t] + 1);  // publish total
    __syncthreads();   // sh reuse below

    // lookback: thread t (< bid) spins for predecessor t's total
    int v = 0;
    if (t < bid) {
        int f;
        do { f = atomicAdd(&g_blob[OFF_FLAGS + t], 0); } while (f == 0);
        v = f - 1;
    }
    sh[t] = v;
    __syncthreads();
    for (int off = SCAN_TPB / 2; off >= 1; off >>= 1) {
        if (t < off) sh[t] += sh[t + off];
        __syncthreads();
    }
    int base = sh[0] + tpre;

    #pragma unroll
    for (int i = 0; i < SCAN_CHUNK; i++) {
        if (i < cnt) {
            g_row_ptr[beg + i] = base;
            base += d[i];
        }
    }
    if (end == n && beg < n) g_row_ptr[n] = base;
}

// Fused kernel: blocks [0, scat_blocks) do the atomic-free scatter (4 edges
// per thread, int4 loads, MLP=4); remaining blocks convert x -> bf16 with
// rs_out pre-scaling. Both depend only on k_scan; fusing overlaps the
// latency-bound scatter with the streaming conversion.
__global__ void k_scx(const int* __restrict__ src, const int* __restrict__ dst, int e,
                      const float* __restrict__ x, int n16, int scat_blocks) {
    if ((int)blockIdx.x < scat_blocks) {
        int base = (blockIdx.x * blockDim.x + threadIdx.x) * 4;
        if (base + 4 <= e) {
            int4 s4 = *(const int4*)(src + base);
            int4 d4 = *(const int4*)(dst + base);
            int4 r4 = *(const int4*)(g_rank + base);
            g_col[g_row_ptr[d4.x] + r4.x] = s4.x;
            g_col[g_row_ptr[d4.y] + r4.y] = s4.y;
            g_col[g_row_ptr[d4.z] + r4.z] = s4.z;
            g_col[g_row_ptr[d4.w] + r4.w] = s4.w;
        } else {
            for (int i = base; i < e; i++)
                g_col[g_row_ptr[dst[i]] + g_rank[i]] = src[i];
        }
    } else {
        int i = (blockIdx.x - scat_blocks) * blockDim.x + threadIdx.x;
        int stride = (gridDim.x - scat_blocks) * blockDim.x;
        const float4* x4 = (const float4*)x;
        uint2* ob = (uint2*)g_xb;
        for (; i < n16; i += stride) {
            float ro = g_rs_out[i >> 4];
            float4 f = x4[i];
            __nv_bfloat162 lo = __floats2bfloat162_rn(f.x * ro, f.y * ro);
            __nv_bfloat162 hi = __floats2bfloat162_rn(f.z * ro, f.w * ro);
            uint2 v;
            v.x = *(unsigned*)&lo;
            v.y = *(unsigned*)&hi;
            ob[i] = v;
        }
    }
}

// rs_out[row]*relu(bn(g_h)) -> g_ab (bf16), conv-1 epilogue, BN inline.
// grid*block multiple of 16 so each thread's channel group is fixed.
__global__ void k_actbf(const float* __restrict__ s1, const float* __restrict__ q1,
                        const float* __restrict__ gma, const float* __restrict__ bet,
                        int n) {
    int i = blockIdx.x * blockDim.x + threadIdx.x;
    int stride = gridDim.x * blockDim.x;
    int cg = i & 15;
    float inv_n = 1.f / (float)n;
    float sc[4], sf[4];
    #pragma unroll
    for (int k = 0; k < 4; k++) {
        int c = cg * 4 + k;
        float mu = s1[c] * inv_n;
        float is = rsqrtf(q1[c] * inv_n - mu * mu + EPSV);
        sc[k] = is * gma[c];
        sf[k] = bet[c] - mu * sc[k];
    }
    const float4* h4 = (const float4*)g_h;
    uint2* ob = (uint2*)g_ab;
    int n16 = n * 16;
    for (; i < n16; i += stride) {
        float ro = g_rs_out[i >> 4];
        float4 h = h4[i];
        float y0 = fmaxf(fmaf(h.x, sc[0], sf[0]), 0.f) * ro;
        float y1 = fmaxf(fmaf(h.y, sc[1], sf[1]), 0.f) * ro;
        float y2 = fmaxf(fmaf(h.z, sc[2], sf[2]), 0.f) * ro;
        float y3 = fmaxf(fmaf(h.w, sc[3], sf[3]), 0.f) * ro;
        __nv_bfloat162 lo = __floats2bfloat162_rn(y0, y1);
        __nv_bfloat162 hi = __floats2bfloat162_rn(y2, y3);
        uint2 v;
        v.x = *(unsigned*)&lo;
        v.y = *(unsigned*)&hi;
        ob[i] = v;
    }
}

// ---------------- pull-mode SpMM (bf16 gather, fp32 accumulate) ----------------
// m[v] = rs_in[v] * sum_{u in N_in(v)} in[u]   (rs_out already folded into in)
// WHICH=0 reads g_xb (conv 1), WHICH=1 reads g_ab (conv 2). Scratch arrays
// referenced in DEVICE code only. One warp per node; lane owns 2 channels.
template <int WHICH>
__global__ void k_spmm(int n) {
    const __nv_bfloat162* __restrict__ in = WHICH ? g_ab : g_xb;
    int warp = (blockIdx.x * blockDim.x + threadIdx.x) >> 5;
    int lane = threadIdx.x & 31;
    if (warp >= n) return;

    int beg = g_row_ptr[warp], end = g_row_ptr[warp + 1];
    float accx = 0.f, accy = 0.f;
    int j = beg;
    for (; j + 8 <= end; j += 8) {
        int u[8];
        #pragma unroll
        for (int i = 0; i < 8; i++) u[i] = __ldg(&g_col[j + i]);
        float2 v[8];
        #pragma unroll
        for (int i = 0; i < 8; i++) {
            __nv_bfloat162 b = __ldg(&in[(size_t)u[i] * 32 + lane]);
            v[i] = __bfloat1622float2(b);
        }
        #pragma unroll
        for (int i = 0; i < 8; i++) {
            accx += v[i].x;
            accy += v[i].y;
        }
    }
    for (; j < end; j++) {
        int u = __ldg(&g_col[j]);
        __nv_bfloat162 b = __ldg(&in[(size_t)u * 32 + lane]);
        float2 v = __bfloat1622float2(b);
        accx += v.x;
        accy += v.y;
    }
    float ri = g_rs_in[warp];
    *(float2*)(g_m + (size_t)warp * 64 + lane * 2) = make_float2(accx * ri, accy * ri);
}

// ---------------- f32x2 GEMM (g_m @ W + b -> g_h) with fused BN statistics ----------------
__global__ void k_gemm(const float* __restrict__ W, const float* __restrict__ bias,
                       float* __restrict__ sumbuf, float* __restrict__ sqbuf, int n) {
    __shared__ float Wt[64][66];
    __shared__ float s_sum[16][64];
    __shared__ float s_sq[16][64];
    int t = threadIdx.x;
    for (int idx = t; idx < 4096; idx += 256) {
        int k = idx >> 6, jj = idx & 63;
        Wt[jj][k] = W[idx];
    }
    __syncthreads();

    int jg = t & 15, rslot = t >> 4;
    int row0 = blockIdx.x * 64 + rslot * 4;

    const ull* m0 = (const ull*)(g_m + (size_t)(row0 + 0) * 64);
    const ull* m1 = (const ull*)(g_m + (size_t)(row0 + 1) * 64);
    const ull* m2p = (const ull*)(g_m + (size_t)(row0 + 2) * 64);
    const ull* m3 = (const ull*)(g_m + (size_t)(row0 + 3) * 64);
    bool val0 = row0 + 0 < n, val1 = row0 + 1 < n, val2 = row0 + 2 < n, val3 = row0 + 3 < n;

    ull acc[4][4];
    #pragma unroll
    for (int r = 0; r < 4; r++)
        #pragma unroll
        for (int i = 0; i < 4; i++) acc[r][i] = 0ULL;

    #pragma unroll 4
    for (int k2 = 0; k2 < 32; k2++) {
        ull a0 = val0 ? m0[k2] : 0ULL;
        ull a1 = val1 ? m1[k2] : 0ULL;
        ull a2 = val2 ? m2p[k2] : 0ULL;
        ull a3 = val3 ? m3[k2] : 0ULL;
        #pragma unroll
        for (int i = 0; i < 4; i++) {
            ull w2 = *(const ull*)&Wt[jg + 16 * i][k2 * 2];
            acc[0][i] = f2fma(a0, w2, acc[0][i]);
            acc[1][i] = f2fma(a1, w2, acc[1][i]);
            acc[2][i] = f2fma(a2, w2, acc[2][i]);
            acc[3][i] = f2fma(a3, w2, acc[3][i]);
        }
    }

    float ls[4] = {0, 0, 0, 0}, lq[4] = {0, 0, 0, 0};
    bool vr[4] = {val0, val1, val2, val3};
    #pragma unroll
    for (int r = 0; r < 4; r++) {
        if (vr[r]) {
            int row = row0 + r;
            #pragma unroll
            for (int i = 0; i < 4; i++) {
                int c = jg + 16 * i;
                float lo, hi;
                f2unpack(acc[r][i], lo, hi);
                float v = lo + hi + bias[c];
                g_h[(size_t)row * 64 + c] = v;
                ls[i] += v;
                lq[i] += v * v;
            }
        }
    }
    #pragma unroll
    for (int i = 0; i < 4; i++) {
        int c = jg + 16 * i;
        s_sum[rslot][c] = ls[i];
        s_sq[rslot][c]  = lq[i];
    }
    __syncthreads();
    if (t < 64) {
        float a = 0, q = 0;
        #pragma unroll
        for (int r = 0; r < 16; r++) { a += s_sum[r][t]; q += s_sq[r][t]; }
        atomicAdd(&sumbuf[t], a);
        atomicAdd(&sqbuf[t], q);
    }
}

// ---------------- fused conv-2 readout + classifier ----------------
__global__ void k_colsum_final(const float* __restrict__ s2, const float* __restrict__ q2,
                               const float* __restrict__ gma, const float* __restrict__ bet,
                               float* __restrict__ colsum, int* __restrict__ done,
                               const float* __restrict__ Wc, const float* __restrict__ bc,
                               float* __restrict__ out, int n) {
    int cg = threadIdx.x & 15;
    int rl = threadIdx.x >> 4;
    float inv_n = 1.f / (float)n;
    float4 gm4 = ((const float4*)gma)[cg];
    float4 be4 = ((const float4*)bet)[cg];
    float4 s4  = ((const float4*)s2)[cg];
    float4 q4  = ((const float4*)q2)[cg];
    float4 mu4, is4;
    mu4.x = s4.x * inv_n; is4.x = rsqrtf(q4.x * inv_n - mu4.x * mu4.x + EPSV);
    mu4.y = s4.y * inv_n; is4.y = rsqrtf(q4.y * inv_n - mu4.y * mu4.y + EPSV);
    mu4.z = s4.z * inv_n; is4.z = rsqrtf(q4.z * inv_n - mu4.z * mu4.z + EPSV);
    mu4.w = s4.w * inv_n; is4.w = rsqrtf(q4.w * inv_n - mu4.w * mu4.w + EPSV);
    float4 sc, sf;
    sc.x = is4.x * gm4.x; sf.x = be4.x - mu4.x * sc.x;
    sc.y = is4.y * gm4.y; sf.y = be4.y - mu4.y * sc.y;
    sc.z = is4.z * gm4.z; sf.z = be4.z - mu4.z * sc.z;
    sc.w = is4.w * gm4.w; sf.w = be4.w - mu4.w * sc.w;

    float4 acc = make_float4(0.f, 0.f, 0.f, 0.f);
    for (int row = blockIdx.x * 16 + rl; row < n; row += gridDim.x * 16) {
        float4 h = ((const float4*)(g_h + (size_t)row * 64))[cg];
        acc.x += fmaxf(fmaf(h.x, sc.x, sf.x), 0.f);
        acc.y += fmaxf(fmaf(h.y, sc.y, sf.y), 0.f);
        acc.z += fmaxf(fmaf(h.z, sc.z, sf.z), 0.f);
        acc.w += fmaxf(fmaf(h.w, sc.w, sf.w), 0.f);
    }
    __shared__ float s[16][64];
    s[rl][cg * 4 + 0] = acc.x; s[rl][cg * 4 + 1] = acc.y;
    s[rl][cg * 4 + 2] = acc.z; s[rl][cg * 4 + 3] = acc.w;
    __syncthreads();
    if (threadIdx.x < 64) {
        float tsum = 0;
        #pragma unroll
        for (int r = 0; r < 16; r++) tsum += s[r][threadIdx.x];
        atomicAdd(&colsum[threadIdx.x], tsum);
    }
    __threadfence();
    __syncthreads();
    __shared__ int is_last;
    if (threadIdx.x == 0) {
        int prev = atomicAdd(done, 1);
        is_last = (prev == gridDim.x - 1);
    }
    __syncthreads();
    if (is_last) {
        __shared__ float s0[64], s1[64];
        if (threadIdx.x < 64) {
            int t = threadIdx.x;
            float v = atomicAdd(&colsum[t], 0.0f) * inv_n;   // L2-coherent read
            s0[t] = v * Wc[t * 2 + 0];
            s1[t] = v * Wc[t * 2 + 1];
        }
        __syncthreads();
        if (threadIdx.x == 0) {
            float a = 0.f, b = 0.f;
            for (int k = 0; k < 64; k++) { a += s0[k]; b += s1[k]; }
            out[0] = a + bc[0];
            out[1] = b + bc[1];
        }
    }
}

// ---------------- launch ----------------
extern "C" void kernel_launch(void* const* d_in, const int* in_sizes, int n_in,
                              void* d_out, int out_size) {
    const float* x   = (const float*)d_in[0];
    const int*   src = (const int*)d_in[1];
    const int*   dst = (const int*)d_in[2];
    const float* W1  = (const float*)d_in[3];
    const float* b1  = (const float*)d_in[4];
    const float* g1  = (const float*)d_in[5];
    const float* be1 = (const float*)d_in[6];
    const float* W2  = (const float*)d_in[7];
    const float* b2  = (const float*)d_in[8];
    const float* g2  = (const float*)d_in[9];
    const float* be2 = (const float*)d_in[10];
    const float* Wc  = (const float*)d_in[11];
    const float* bc  = (const float*)d_in[12];
    float* out = (float*)d_out;

    int n = in_sizes[0] / 64;
    int e = in_sizes[1];

    int eb = (e + 255) / 256;
    int scat_blocks = (e + 1023) / 1024;   // 4 edges per thread
    int spmm_blocks = (n + 7) / 8;
    int gemm_blocks = (n + 63) / 64;

    int* blob_d;
    cudaGetSymbolAddress((void**)&blob_d, g_blob);
    float* ds1  = (float*)(blob_d + OFF_STATS);
    float* dq1  = ds1 + 64;
    float* ds2  = ds1 + 128;
    float* dq2  = ds1 + 192;
    float* dcol = ds1 + 256;
    int*   ddone = blob_d + OFF_STATS + 320;

    // zero degrees + stats + counter + scan flags in one memset node
    cudaMemsetAsync(blob_d, 0, (size_t)BLOB_INTS * sizeof(int));

    // graph preprocessing (CSR by dst, rank-based) — reused by both convs
    k_deg<<<eb, 256>>>(src, dst, e);
    k_scan<<<SCAN_BLOCKS, SCAN_TPB>>>(n);
    k_scx<<<scat_blocks + 512, 256>>>(src, dst, e, x, n * 16, scat_blocks);

    // conv 1 (bf16 gather of rs_out*x)
    k_spmm<0><<<spmm_blocks, 256>>>(n);
    k_gemm<<<gemm_blocks, 256>>>(W1, b1, ds1, dq1, n);

    // conv 2 (bf16 gather of rs_out*relu(bn(h1)))
    k_actbf<<<512, 256>>>(ds1, dq1, g1, be1, n);
    k_spmm<1><<<spmm_blocks, 256>>>(n);
    k_gemm<<<gemm_blocks, 256>>>(W2, b2, ds2, dq2, n);

    // fused readout + classifier
    k_colsum_final<<<512, 256>>>(ds2, dq2, g2, be2, dcol, ddone, Wc, bc, out, n);
    (void)n_in; (void)out_size;
}

// round 17
// speedup vs baseline: 1.3168x; 1.3168x over previous
#include <cuda_runtime.h>
#include <cuda_bf16.h>

// CoPEModel GCN on GB300.
// CSR-build (rank-recorded histogram -> 2-pass scan -> atomic-free int4
// scatter) + bf16-gather pull-mode SpMM (int4 index loads, packed f32x2
// accumulation) with rs_out pre-scaled into features + f32x2 GEMM with fused
// BN stats + fused colsum/readout.
// Inputs (metadata order): x, src, dst, W1, b1, g1, be1, W2, b2, g2, be2, Wc, bc
// Output: [1,2] float32.

#define NMAX 100000
#define EMAX 1600000

#define SCAN_BLOCKS 128
#define SCAN_TPB    256
#define SCAN_T      (SCAN_BLOCKS * SCAN_TPB)   // 32768 scan threads
#define SCAN_CHUNK  4                          // ceil(100000/32768)

#define EPSV 1e-5f

typedef unsigned long long ull;

// ---- zero-initialized-per-launch blob (single memset node) ----
// [0,N): deg_out  [N,2N): deg_in  [2N..): s1,q1,s2,q2,colsum,done
#define OFF_DEG_OUT 0
#define OFF_DEG_IN  NMAX
#define OFF_STATS   (2 * NMAX)
#define BLOB_INTS   (2 * NMAX + 384)
__device__ __align__(16) int g_blob[BLOB_INTS];

__device__ __align__(16) float g_rs_out[NMAX];
__device__ __align__(16) float g_rs_in[NMAX];
__device__ __align__(16) int   g_row_ptr[NMAX + 1];
__device__ __align__(16) int   g_rank[EMAX];            // intra-dst rank of each edge
__device__ __align__(16) int   g_col[EMAX];             // CSR column (src) indices
__device__ __align__(16) int   g_tpre[SCAN_T];
__device__ __align__(16) int   g_bsum[SCAN_BLOCKS];
__device__ __align__(16) __nv_bfloat162 g_xb[(size_t)NMAX * 32];  // bf16 rs_out*x
__device__ __align__(16) __nv_bfloat162 g_ab[(size_t)NMAX * 32];  // bf16 rs_out*relu(bn(h1))
__device__ __align__(16) float g_m[(size_t)NMAX * 64];  // aggregated messages
__device__ __align__(16) float g_h[(size_t)NMAX * 64];  // post-GEMM

// ---------------- packed f32x2 helpers ----------------
__device__ __forceinline__ void f2unpack(ull v, float& a, float& b) {
    asm("mov.b64 {%0, %1}, %2;" : "=f"(a), "=f"(b) : "l"(v));
}
__device__ __forceinline__ ull f2fma(ull a, ull b, ull c) {
    ull d; asm("fma.rn.f32x2 %0, %1, %2, %3;" : "=l"(d) : "l"(a), "l"(b), "l"(c)); return d;
}
// bf16x2 word -> packed f32x2 (lo = b<<16, hi = b & 0xffff0000)
__device__ __forceinline__ ull bf2f2(unsigned b) {
    unsigned lo = b << 16;
    unsigned hi = b & 0xffff0000u;
    ull v; asm("mov.b64 %0, {%1, %2};" : "=l"(v) : "r"(lo), "r"(hi));
    return v;
}
__device__ __forceinline__ void f2add(ull& acc, ull v) {
    asm("add.rn.f32x2 %0, %0, %1;" : "+l"(acc) : "l"(v));
}

// ---------------- graph preprocessing ----------------

// Degree histogram; the deg_in atomic RETURNS this edge's rank within its dst
// bucket, recorded coalesced — the scatter then needs no atomic at all.
__global__ void k_deg(const int* __restrict__ src, const int* __restrict__ dst, int e) {
    int i = blockIdx.x * blockDim.x + threadIdx.x;
    if (i < e) {
        g_rank[i] = atomicAdd(&g_blob[OFF_DEG_IN + dst[i]], 1);
        atomicAdd(&g_blob[OFF_DEG_OUT + src[i]], 1);
    }
}

// Phase 1: per-thread chunk sums + rsqrt degrees + block-level scan.
__global__ void k_scan_p1(int n) {
    __shared__ int sh[SCAN_TPB];
    int t = threadIdx.x;
    int g = blockIdx.x * SCAN_TPB + t;
    int beg = g * SCAN_CHUNK;
    int end = min(beg + SCAN_CHUNK, n);
    int s = 0;
    for (int i = beg; i < end; i++) {
        int di = g_blob[OFF_DEG_IN + i];
        s += di;
        g_rs_in[i]  = rsqrtf((float)max(di, 1));
        g_rs_out[i] = rsqrtf((float)max(g_blob[OFF_DEG_OUT + i], 1));
    }
    sh[t] = s;
    __syncthreads();
    for (int off = 1; off < SCAN_TPB; off <<= 1) {
        int v = (t >= off) ? sh[t - off] : 0;
        __syncthreads();
        sh[t] += v;
        __syncthreads();
    }
    g_tpre[g] = sh[t] - s;
    if (t == SCAN_TPB - 1) g_bsum[blockIdx.x] = sh[t];
}

// Phase 3 (phase 2 inlined): each block reduces its block-sum prefix, writes row_ptr.
__global__ void k_scan_p3(int n) {
    __shared__ int sb[SCAN_BLOCKS];
    int t = threadIdx.x;
    if (t < SCAN_BLOCKS) sb[t] = (t < blockIdx.x) ? g_bsum[t] : 0;
    __syncthreads();
    for (int off = SCAN_BLOCKS / 2; off >= 1; off >>= 1) {
        if (t < off) sb[t] += sb[t + off];
        __syncthreads();
    }
    int bpre = sb[0];
    int g = blockIdx.x * SCAN_TPB + t;
    int beg = g * SCAN_CHUNK;
    int end = min(beg + SCAN_CHUNK, n);
    int base = bpre + g_tpre[g];
    for (int i = beg; i < end; i++) {
        g_row_ptr[i] = base;
        base += g_blob[OFF_DEG_IN + i];
    }
    if (end == n && beg < n) g_row_ptr[n] = base;
}

// Atomic-free scatter: position = row_ptr[dst] + recorded rank.
// 4 edges per thread via int4 loads -> 4 independent gather/store chains.
__global__ void k_scatter(const int* __restrict__ src, const int* __restrict__ dst, int e) {
    int base = (blockIdx.x * blockDim.x + threadIdx.x) * 4;
    if (base + 4 <= e) {
        int4 s4 = *(const int4*)(src + base);
        int4 d4 = *(const int4*)(dst + base);
        int4 r4 = *(const int4*)(g_rank + base);
        g_col[g_row_ptr[d4.x] + r4.x] = s4.x;
        g_col[g_row_ptr[d4.y] + r4.y] = s4.y;
        g_col[g_row_ptr[d4.z] + r4.z] = s4.z;
        g_col[g_row_ptr[d4.w] + r4.w] = s4.w;
    } else {
        for (int i = base; i < e; i++)
            g_col[g_row_ptr[dst[i]] + g_rank[i]] = src[i];
    }
}

// ---------------- bf16 conversion passes (rs_out pre-scaled) ----------------

// rs_out[row]*x (fp32) -> g_xb (bf16). n*16 float4 elements; row = i>>4.
__global__ void k_x2bf(const float* __restrict__ x, int n16) {
    int i = blockIdx.x * blockDim.x + threadIdx.x;
    int stride = gridDim.x * blockDim.x;
    const float4* x4 = (const float4*)x;
    uint2* ob = (uint2*)g_xb;
    for (; i < n16; i += stride) {
        float ro = g_rs_out[i >> 4];
        float4 f = x4[i];
        __nv_bfloat162 lo = __floats2bfloat162_rn(f.x * ro, f.y * ro);
        __nv_bfloat162 hi = __floats2bfloat162_rn(f.z * ro, f.w * ro);
        uint2 v;
        v.x = *(unsigned*)&lo;
        v.y = *(unsigned*)&hi;
        ob[i] = v;
    }
}

// rs_out[row]*relu(bn(g_h)) -> g_ab (bf16), conv-1 epilogue, BN inline.
// grid*block multiple of 16 so each thread's channel group is fixed.
__global__ void k_actbf(const float* __restrict__ s1, const float* __restrict__ q1,
                        const float* __restrict__ gma, const float* __restrict__ bet,
                        int n) {
    int i = blockIdx.x * blockDim.x + threadIdx.x;
    int stride = gridDim.x * blockDim.x;
    int cg = i & 15;
    float inv_n = 1.f / (float)n;
    float sc[4], sf[4];
    #pragma unroll
    for (int k = 0; k < 4; k++) {
        int c = cg * 4 + k;
        float mu = s1[c] * inv_n;
        float is = rsqrtf(q1[c] * inv_n - mu * mu + EPSV);
        sc[k] = is * gma[c];
        sf[k] = bet[c] - mu * sc[k];
    }
    const float4* h4 = (const float4*)g_h;
    uint2* ob = (uint2*)g_ab;
    int n16 = n * 16;
    for (; i < n16; i += stride) {
        float ro = g_rs_out[i >> 4];
        float4 h = h4[i];
        float y0 = fmaxf(fmaf(h.x, sc[0], sf[0]), 0.f) * ro;
        float y1 = fmaxf(fmaf(h.y, sc[1], sf[1]), 0.f) * ro;
        float y2 = fmaxf(fmaf(h.z, sc[2], sf[2]), 0.f) * ro;
        float y3 = fmaxf(fmaf(h.w, sc[3], sf[3]), 0.f) * ro;
        __nv_bfloat162 lo = __floats2bfloat162_rn(y0, y1);
        __nv_bfloat162 hi = __floats2bfloat162_rn(y2, y3);
        uint2 v;
        v.x = *(unsigned*)&lo;
        v.y = *(unsigned*)&hi;
        ob[i] = v;
    }
}

// ---------------- pull-mode SpMM (bf16 gather, packed f32x2 accumulate) ------
// m[v] = rs_in[v] * sum_{u in N_in(v)} in[u]   (rs_out already folded into in)
// One warp per node; lane owns 2 channels (one bf16x2 word). Issue-bound, so
// minimize instructions/edge: int4 index loads (0.25 inst/edge), bf16x2 ->
// f32x2 via shift/mask (2 ALU), one add.rn.f32x2 (fp32-exact, 2 ch per issue).
// Two accumulators break the dependency chain; batches of 8 keep MLP=8.
template <int WHICH>
__global__ void k_spmm(int n) {
    const unsigned* __restrict__ in =
        (const unsigned*)(WHICH ? g_ab : g_xb);
    int warp = (blockIdx.x * blockDim.x + threadIdx.x) >> 5;
    int lane = threadIdx.x & 31;
    if (warp >= n) return;
    const unsigned* __restrict__ inl = in + lane;

    int beg = g_row_ptr[warp], end = g_row_ptr[warp + 1];
    ull acc0 = 0, acc1 = 0;

    int j = beg;
    int jal = min((beg + 3) & ~3, end);          // scalar prologue to 16B alignment
    for (; j < jal; j++) {
        unsigned b = __ldg(inl + (size_t)__ldg(&g_col[j]) * 32);
        f2add(acc0, bf2f2(b));
    }
    for (; j + 8 <= end; j += 8) {
        int4 u0 = *(const int4*)(g_col + j);
        int4 u1 = *(const int4*)(g_col + j + 4);
        unsigned b0 = __ldg(inl + (size_t)u0.x * 32);
        unsigned b1 = __ldg(inl + (size_t)u0.y * 32);
        unsigned b2 = __ldg(inl + (size_t)u0.z * 32);
        unsigned b3 = __ldg(inl + (size_t)u0.w * 32);
        unsigned b4 = __ldg(inl + (size_t)u1.x * 32);
        unsigned b5 = __ldg(inl + (size_t)u1.y * 32);
        unsigned b6 = __ldg(inl + (size_t)u1.z * 32);
        unsigned b7 = __ldg(inl + (size_t)u1.w * 32);
        f2add(acc0, bf2f2(b0)); f2add(acc1, bf2f2(b1));
        f2add(acc0, bf2f2(b2)); f2add(acc1, bf2f2(b3));
        f2add(acc0, bf2f2(b4)); f2add(acc1, bf2f2(b5));
        f2add(acc0, bf2f2(b6)); f2add(acc1, bf2f2(b7));
    }
    if (j + 4 <= end) {
        int4 u0 = *(const int4*)(g_col + j);
        unsigned b0 = __ldg(inl + (size_t)u0.x * 32);
        unsigned b1 = __ldg(inl + (size_t)u0.y * 32);
        unsigned b2 = __ldg(inl + (size_t)u0.z * 32);
        unsigned b3 = __ldg(inl + (size_t)u0.w * 32);
        f2add(acc0, bf2f2(b0)); f2add(acc1, bf2f2(b1));
        f2add(acc0, bf2f2(b2)); f2add(acc1, bf2f2(b3));
        j += 4;
    }
    for (; j < end; j++) {
        unsigned b = __ldg(inl + (size_t)__ldg(&g_col[j]) * 32);
        f2add(acc0, bf2f2(b));
    }

    f2add(acc0, acc1);
    float accx, accy;
    f2unpack(acc0, accx, accy);
    float ri = g_rs_in[warp];
    *(float2*)(g_m + (size_t)warp * 64 + lane * 2) = make_float2(accx * ri, accy * ri);
}

// ---------------- f32x2 GEMM (g_m @ W + b -> g_h) with fused BN statistics ----------------
__global__ void k_gemm(const float* __restrict__ W, const float* __restrict__ bias,
                       float* __restrict__ sumbuf, float* __restrict__ sqbuf, int n) {
    __shared__ float Wt[64][66];
    __shared__ float s_sum[16][64];
    __shared__ float s_sq[16][64];
    int t = threadIdx.x;
    for (int idx = t; idx < 4096; idx += 256) {
        int k = idx >> 6, jj = idx & 63;
        Wt[jj][k] = W[idx];
    }
    __syncthreads();

    int jg = t & 15, rslot = t >> 4;
    int row0 = blockIdx.x * 64 + rslot * 4;

    const ull* m0 = (const ull*)(g_m + (size_t)(row0 + 0) * 64);
    const ull* m1 = (const ull*)(g_m + (size_t)(row0 + 1) * 64);
    const ull* m2p = (const ull*)(g_m + (size_t)(row0 + 2) * 64);
    const ull* m3 = (const ull*)(g_m + (size_t)(row0 + 3) * 64);
    bool val0 = row0 + 0 < n, val1 = row0 + 1 < n, val2 = row0 + 2 < n, val3 = row0 + 3 < n;

    ull acc[4][4];
    #pragma unroll
    for (int r = 0; r < 4; r++)
        #pragma unroll
        for (int i = 0; i < 4; i++) acc[r][i] = 0ULL;

    #pragma unroll 4
    for (int k2 = 0; k2 < 32; k2++) {
        ull a0 = val0 ? m0[k2] : 0ULL;
        ull a1 = val1 ? m1[k2] : 0ULL;
        ull a2 = val2 ? m2p[k2] : 0ULL;
        ull a3 = val3 ? m3[k2] : 0ULL;
        #pragma unroll
        for (int i = 0; i < 4; i++) {
            ull w2 = *(const ull*)&Wt[jg + 16 * i][k2 * 2];
            acc[0][i] = f2fma(a0, w2, acc[0][i]);
            acc[1][i] = f2fma(a1, w2, acc[1][i]);
            acc[2][i] = f2fma(a2, w2, acc[2][i]);
            acc[3][i] = f2fma(a3, w2, acc[3][i]);
        }
    }

    float ls[4] = {0, 0, 0, 0}, lq[4] = {0, 0, 0, 0};
    bool vr[4] = {val0, val1, val2, val3};
    #pragma unroll
    for (int r = 0; r < 4; r++) {
        if (vr[r]) {
            int row = row0 + r;
            #pragma unroll
            for (int i = 0; i < 4; i++) {
                int c = jg + 16 * i;
                float lo, hi;
                f2unpack(acc[r][i], lo, hi);
                float v = lo + hi + bias[c];
                g_h[(size_t)row * 64 + c] = v;
                ls[i] += v;
                lq[i] += v * v;
            }
        }
    }
    #pragma unroll
    for (int i = 0; i < 4; i++) {
        int c = jg + 16 * i;
        s_sum[rslot][c] = ls[i];
        s_sq[rslot][c]  = lq[i];
    }
    __syncthreads();
    if (t < 64) {
        float a = 0, q = 0;
        #pragma unroll
        for (int r = 0; r < 16; r++) { a += s_sum[r][t]; q += s_sq[r][t]; }
        atomicAdd(&sumbuf[t], a);
        atomicAdd(&sqbuf[t], q);
    }
}

// ---------------- fused conv-2 readout + classifier ----------------
__global__ void k_colsum_final(const float* __restrict__ s2, const float* __restrict__ q2,
                               const float* __restrict__ gma, const float* __restrict__ bet,
                               float* __restrict__ colsum, int* __restrict__ done,
                               const float* __restrict__ Wc, const float* __restrict__ bc,
                               float* __restrict__ out, int n) {
    int cg = threadIdx.x & 15;
    int rl = threadIdx.x >> 4;
    float inv_n = 1.f / (float)n;
    float4 gm4 = ((const float4*)gma)[cg];
    float4 be4 = ((const float4*)bet)[cg];
    float4 s4  = ((const float4*)s2)[cg];
    float4 q4  = ((const float4*)q2)[cg];
    float4 mu4, is4;
    mu4.x = s4.x * inv_n; is4.x = rsqrtf(q4.x * inv_n - mu4.x * mu4.x + EPSV);
    mu4.y = s4.y * inv_n; is4.y = rsqrtf(q4.y * inv_n - mu4.y * mu4.y + EPSV);
    mu4.z = s4.z * inv_n; is4.z = rsqrtf(q4.z * inv_n - mu4.z * mu4.z + EPSV);
    mu4.w = s4.w * inv_n; is4.w = rsqrtf(q4.w * inv_n - mu4.w * mu4.w + EPSV);
    float4 sc, sf;
    sc.x = is4.x * gm4.x; sf.x = be4.x - mu4.x * sc.x;
    sc.y = is4.y * gm4.y; sf.y = be4.y - mu4.y * sc.y;
    sc.z = is4.z * gm4.z; sf.z = be4.z - mu4.z * sc.z;
    sc.w = is4.w * gm4.w; sf.w = be4.w - mu4.w * sc.w;

    float4 acc = make_float4(0.f, 0.f, 0.f, 0.f);
    for (int row = blockIdx.x * 16 + rl; row < n; row += gridDim.x * 16) {
        float4 h = ((const float4*)(g_h + (size_t)row * 64))[cg];
        acc.x += fmaxf(fmaf(h.x, sc.x, sf.x), 0.f);
        acc.y += fmaxf(fmaf(h.y, sc.y, sf.y), 0.f);
        acc.z += fmaxf(fmaf(h.z, sc.z, sf.z), 0.f);
        acc.w += fmaxf(fmaf(h.w, sc.w, sf.w), 0.f);
    }
    __shared__ float s[16][64];
    s[rl][cg * 4 + 0] = acc.x; s[rl][cg * 4 + 1] = acc.y;
    s[rl][cg * 4 + 2] = acc.z; s[rl][cg * 4 + 3] = acc.w;
    __syncthreads();
    if (threadIdx.x < 64) {
        float tsum = 0;
        #pragma unroll
        for (int r = 0; r < 16; r++) tsum += s[r][threadIdx.x];
        atomicAdd(&colsum[threadIdx.x], tsum);
    }
    __threadfence();
    __syncthreads();
    __shared__ int is_last;
    if (threadIdx.x == 0) {
        int prev = atomicAdd(done, 1);
        is_last = (prev == gridDim.x - 1);
    }
    __syncthreads();
    if (is_last) {
        __shared__ float s0[64], s1[64];
        if (threadIdx.x < 64) {
            int t = threadIdx.x;
            float v = atomicAdd(&colsum[t], 0.0f) * inv_n;   // L2-coherent read
            s0[t] = v * Wc[t * 2 + 0];
            s1[t] = v * Wc[t * 2 + 1];
        }
        __syncthreads();
        if (threadIdx.x == 0) {
            float a = 0.f, b = 0.f;
            for (int k = 0; k < 64; k++) { a += s0[k]; b += s1[k]; }
            out[0] = a + bc[0];
            out[1] = b + bc[1];
        }
    }
}

// ---------------- launch ----------------
extern "C" void kernel_launch(void* const* d_in, const int* in_sizes, int n_in,
                              void* d_out, int out_size) {
    const float* x   = (const float*)d_in[0];
    const int*   src = (const int*)d_in[1];
    const int*   dst = (const int*)d_in[2];
    const float* W1  = (const float*)d_in[3];
    const float* b1  = (const float*)d_in[4];
    const float* g1  = (const float*)d_in[5];
    const float* be1 = (const float*)d_in[6];
    const float* W2  = (const float*)d_in[7];
    const float* b2  = (const float*)d_in[8];
    const float* g2  = (const float*)d_in[9];
    const float* be2 = (const float*)d_in[10];
    const float* Wc  = (const float*)d_in[11];
    const float* bc  = (const float*)d_in[12];
    float* out = (float*)d_out;

    int n = in_sizes[0] / 64;
    int e = in_sizes[1];

    int eb = (e + 255) / 256;
    int scat_blocks = (e + 1023) / 1024;   // 4 edges per thread
    int spmm_blocks = (n + 7) / 8;
    int gemm_blocks = (n + 63) / 64;

    int* blob_d;
    cudaGetSymbolAddress((void**)&blob_d, g_blob);
    float* ds1  = (float*)(blob_d + OFF_STATS);
    float* dq1  = ds1 + 64;
    float* ds2  = ds1 + 128;
    float* dq2  = ds1 + 192;
    float* dcol = ds1 + 256;
    int*   ddone = blob_d + OFF_STATS + 320;

    // zero degrees + stats + counter in one memset node
    cudaMemsetAsync(blob_d, 0, (size_t)BLOB_INTS * sizeof(int));

    // graph preprocessing (CSR by dst, rank-based) — reused by both convs
    k_deg<<<eb, 256>>>(src, dst, e);
    k_scan_p1<<<SCAN_BLOCKS, SCAN_TPB>>>(n);
    k_scan_p3<<<SCAN_BLOCKS, SCAN_TPB>>>(n);
    k_scatter<<<scat_blocks, 256>>>(src, dst, e);

    // conv 1 (bf16 gather of rs_out*x)
    k_x2bf<<<512, 256>>>(x, n * 16);
    k_spmm<0><<<spmm_blocks, 256>>>(n);
    k_gemm<<<gemm_blocks, 256>>>(W1, b1, ds1, dq1, n);

    // conv 2 (bf16 gather of rs_out*relu(bn(h1)))
    k_actbf<<<512, 256>>>(ds1, dq1, g1, be1, n);
    k_spmm<1><<<spmm_blocks, 256>>>(n);
    k_gemm<<<gemm_blocks, 256>>>(W2, b2, ds2, dq2, n);

    // fused readout + classifier
    k_colsum_final<<<512, 256>>>(ds2, dq2, g2, be2, dcol, ddone, Wc, bc, out, n);
    (void)n_in; (void)out_size;
}